// round 14
// baseline (speedup 1.0000x reference)
#include <cuda_runtime.h>
#include <math_constants.h>
#include <string.h>

#define NSEQ 16          // B*H
#define SEQL 1024        // L
#define DIM  64          // D
#define CHK  128         // chunk size
#define NCHK (SEQL/CHK)  // 8
#define D2   128         // 2*DIM
#define NBLK (NSEQ*NCHK) // 128 blocks

__device__ float g_S[NSEQ*NCHK*D2*DIM];
__device__ float g_z[NSEQ*NCHK*D2];
__device__ unsigned int g_bar;   // zero-init; monotone across replays

__device__ __forceinline__ float4 relu4(float4 a){
    a.x = fmaxf(a.x,0.f); a.y = fmaxf(a.y,0.f);
    a.z = fmaxf(a.z,0.f); a.w = fmaxf(a.w,0.f);
    return a;
}
typedef unsigned long long u64c;
__device__ __forceinline__ u64c ffma2(u64c a, u64c b, u64c c){
    u64c d;
    asm("fma.rn.f32x2 %0, %1, %2, %3;" : "=l"(d) : "l"(a), "l"(b), "l"(c));
    return d;
}
__device__ __forceinline__ u64c pk(float x, float y){
    float2 t = make_float2(x, y); u64c r; memcpy(&r, &t, 8); return r;
}
__device__ __forceinline__ u64c dupf(float x){ return pk(x, x); }
__device__ __forceinline__ float2 up(u64c d){
    float2 t; memcpy(&t, &d, 8); return t;
}

__device__ __forceinline__ void grid_barrier() {
    __threadfence();
    __syncthreads();
    if (threadIdx.x == 0) {
        unsigned gen = atomicAdd(&g_bar, 1u);
        unsigned target = (gen / NBLK + 1u) * NBLK;
        while (atomicAdd(&g_bar, 0u) < target) { }
    }
    __syncthreads();
    __threadfence();
}

// ---------------------------------------------------------------------------
// Fused kernel. grid = 128 (one block per (seq, chunk)), block = 512.
// ---------------------------------------------------------------------------
__global__ void __launch_bounds__(512,1)
fused_cos_attn(const float* __restrict__ q, const float* __restrict__ k,
               const float* __restrict__ v, float* __restrict__ out) {
    const int blk = blockIdx.x;
    const int n = blk >> 3, c = blk & 7;
    extern __shared__ float sm[];
    float* qT  = sm;                     // [64 d][132] relu(q) transposed
    float* kT  = qT + 64*132;            // [64 d][132] relu(k) transposed; obuf overlay
    float* kx  = kT + 64*132;            // [128 d'][132] kextT; At overlay
    float* V   = kx + 128*132 + 32;      // [128 j][68]
    float* U   = V + 128*68;             // [128 d'][68]  prefix state
    float* sth = U + 128*68;             // 128
    float* cth = sth + 128;              // 128
    float* zext= cth + 128;              // 128
    float* dscr= zext + 128;             // 256 (denominator partials, 2 per l)
    const int tid = threadIdx.x;
    const size_t base = ((size_t)n*SEQL + (size_t)c*CHK)*DIM;
    const float4* q4 = (const float4*)(q + base);
    const float4* k4 = (const float4*)(k + base);
    const float4* v4 = (const float4*)(v + base);

    // ---- Stage: qT/kT plain transposed, kx extended transposed, V row-major --
    {
        const int j = tid & 127;
        const float ang = 1.5707963268f * (float)(c*CHK + j + 1) * (1.f/(float)SEQL);
        const float s = __sinf(ang), cc = __cosf(ang);
        if (tid < 128) { sth[j] = s; cth[j] = cc; }
        #pragma unroll
        for (int it = 0; it < 4; it++) {
            int f = (tid >> 7) + 4*it;       // 0..15
            float4 qq = relu4(q4[j*16 + f]);
            float4 kk = relu4(k4[j*16 + f]);
            float4 vv = relu4(v4[j*16 + f]);
            int d = 4*f;
            qT[(d+0)*132 + j] = qq.x; qT[(d+1)*132 + j] = qq.y;
            qT[(d+2)*132 + j] = qq.z; qT[(d+3)*132 + j] = qq.w;
            kT[(d+0)*132 + j] = kk.x; kT[(d+1)*132 + j] = kk.y;
            kT[(d+2)*132 + j] = kk.z; kT[(d+3)*132 + j] = kk.w;
            kx[(d+0)*132 + j] = kk.x*s;  kx[(d+64)*132 + j] = kk.x*cc;
            kx[(d+1)*132 + j] = kk.y*s;  kx[(d+65)*132 + j] = kk.y*cc;
            kx[(d+2)*132 + j] = kk.z*s;  kx[(d+66)*132 + j] = kk.z*cc;
            kx[(d+3)*132 + j] = kk.w*s;  kx[(d+67)*132 + j] = kk.w*cc;
            *(float4*)&V[j*68 + d] = vv;
        }
    }
    __syncthreads();

    // ---- z[d'] (threads 128..255) concurrent with chunk GEMM (0..127) ----
    if (tid >= 128 && tid < 256) {
        const int dp = tid - 128;
        const float4* row4 = (const float4*)&kx[dp*132];
        float zz = 0.f;
        #pragma unroll 8
        for (int jf = 0; jf < 32; jf++) {
            float4 t = row4[jf];
            zz += t.x + t.y + t.z + t.w;
        }
        g_z[blk*D2 + dp] = zz;
    }

    // ---- Chunk-state GEMM: S[d'][m] = sum_j kx[d'][j]*V[j][m]
    //      128 threads, 8 d' (interleave 16) x 8 m per thread, j-block 2 ----
    if (tid < 128) {
        const int td = tid >> 3, tm8 = tid & 7;   // 16 d-slots x 8 m-groups
        const float4* V4 = (const float4*)V;
        u64c acc[8][4];                           // [r][m-pair]
        #pragma unroll
        for (int r = 0; r < 8; r++)
            #pragma unroll
            for (int mp = 0; mp < 4; mp++) acc[r][mp] = pk(0.f,0.f);

        for (int jb = 0; jb < CHK; jb += 2) {
            float2 kr[8];
            #pragma unroll
            for (int r = 0; r < 8; r++)
                kr[r] = *(const float2*)&kx[(td + 16*r)*132 + jb];
            #pragma unroll
            for (int i = 0; i < 2; i++) {
                int j = jb + i;
                float4 v0 = V4[j*17 + 2*tm8];
                float4 v1 = V4[j*17 + 2*tm8 + 1];
                u64c vp[4] = { pk(v0.x,v0.y), pk(v0.z,v0.w),
                               pk(v1.x,v1.y), pk(v1.z,v1.w) };
                #pragma unroll
                for (int r = 0; r < 8; r++) {
                    u64c kd = dupf(i ? kr[r].y : kr[r].x);
                    #pragma unroll
                    for (int mp = 0; mp < 4; mp++)
                        acc[r][mp] = ffma2(kd, vp[mp], acc[r][mp]);
                }
            }
        }
        float4* oS = (float4*)(g_S + (size_t)blk*D2*DIM);
        #pragma unroll
        for (int r = 0; r < 8; r++) {
            int row = td + 16*r;
            float2 a0 = up(acc[r][0]), a1 = up(acc[r][1]);
            float2 a2 = up(acc[r][2]), a3 = up(acc[r][3]);
            oS[row*16 + 2*tm8]     = make_float4(a0.x,a0.y,a1.x,a1.y);
            oS[row*16 + 2*tm8 + 1] = make_float4(a2.x,a2.y,a3.x,a3.y);
        }
    }

    grid_barrier();

    const float4* qT4 = (const float4*)qT;
    const float4* kT4 = (const float4*)kT;

    // ---- Phase A (wid 0..9, K=64 plain) || U prefix load (wid 10..15) ----
    const int wid = tid >> 5, lane = tid & 31;
    const int wl = (wid >= 1) + (wid >= 3) + (wid >= 6);
    const int wj = wid - (wl*(wl+1))/2;
    const int tl = wl*4 + (lane >> 3);       // 0..15, l-tile of 8
    const int tj = wj*8 + (lane & 7);        // 0..31, j-tile of 4
    const int l0 = tl*8, j0 = tj*4;
    const bool activeA = (wid < 10);
    u64c a2[4][4];                            // [jj][l-pair]
    #pragma unroll
    for (int jj = 0; jj < 4; jj++)
        #pragma unroll
        for (int lp = 0; lp < 4; lp++) a2[jj][lp] = pk(0.f,0.f);

    if (activeA) {
        #pragma unroll 4
        for (int dp = 0; dp < 64; dp++) {
            float4 qa = qT4[dp*33 + 2*tl];
            float4 qb = qT4[dp*33 + 2*tl + 1];
            float4 kA = kT4[dp*33 + tj];
            u64c qp[4] = { pk(qa.x,qa.y), pk(qa.z,qa.w),
                           pk(qb.x,qb.y), pk(qb.z,qb.w) };
            float kv[4] = {kA.x,kA.y,kA.z,kA.w};
            #pragma unroll
            for (int jj = 0; jj < 4; jj++) {
                u64c kd = dupf(kv[jj]);
                #pragma unroll
                for (int lp = 0; lp < 4; lp++)
                    a2[jj][lp] = ffma2(kd, qp[lp], a2[jj][lp]);
            }
        }
    } else {
        // wid 10..15 (192 threads): U = sum of chunks 0..c-1, zext prefix.
        const int t = tid - 320;
        const float4* gSn = (const float4*)(g_S + (size_t)(n*NCHK)*D2*DIM);
        float4* U4w = (float4*)U;
        for (int i4 = t; i4 < 2048; i4 += 192) {
            float4 acc = make_float4(0.f,0.f,0.f,0.f);
            for (int cc = 0; cc < c; cc++) {
                float4 x = gSn[(size_t)cc*2048 + i4];
                acc.x += x.x; acc.y += x.y; acc.z += x.z; acc.w += x.w;
            }
            U4w[(i4 >> 4)*17 + (i4 & 15)] = acc;
        }
        if (t < D2) {
            float zz = 0.f;
            for (int cc = 0; cc < c; cc++) zz += g_z[(n*NCHK + cc)*D2 + t];
            zext[t] = zz;
        }
    }
    __syncthreads();

    // ---- At store with cos-identity epilogue (XOR-swizzled float4 groups) ----
    float4* At4 = (float4*)kx;
    if (activeA) {
        float slv[8], clv[8];
        #pragma unroll
        for (int i = 0; i < 8; i++) { slv[i] = sth[l0+i]; clv[i] = cth[l0+i]; }
        #pragma unroll
        for (int jj = 0; jj < 4; jj++) {
            int j = j0 + jj;
            int swz = (j >> 3) & 7;
            float sj = sth[j], cj = cth[j];
            float w[8];
            #pragma unroll
            for (int lp = 0; lp < 4; lp++) {
                float2 p = up(a2[jj][lp]);
                float f0 = fmaf(clv[2*lp],   cj, slv[2*lp]*sj);
                float f1 = fmaf(clv[2*lp+1], cj, slv[2*lp+1]*sj);
                w[2*lp]   = (j <= l0 + 2*lp)     ? p.x * f0 : 0.f;
                w[2*lp+1] = (j <= l0 + 2*lp + 1) ? p.y * f1 : 0.f;
            }
            At4[j*33 + ((2*tl)   ^ swz)] = make_float4(w[0],w[1],w[2],w[3]);
            At4[j*33 + ((2*tl+1) ^ swz)] = make_float4(w[4],w[5],w[6],w[7]);
        }
    }
    __syncthreads();

    // ---- Concurrent tail: AV (wid 0..3) || qU (wid 4..7) || denom (wid 8..15)
    u64c oav[4][8];                          // AV accumulators, live into combine
    const int tB  = tid & 127;
    const int tlB = tB >> 3, tmB = tB & 7;   // 16 l-tiles x 8 m-groups
    const int lB0 = tlB*8;

    if (tid < 128) {
        // AV: 8l x 8m, causal-truncated
        #pragma unroll
        for (int lp = 0; lp < 4; lp++)
            #pragma unroll
            for (int m = 0; m < 8; m++) oav[lp][m] = pk(0.f,0.f);
        const float4* V4c = (const float4*)V;
        const int jmax = lB0 + 8;
        for (int j = 0; j < jmax; j++) {
            int swz = (j >> 3) & 7;
            float4 A0 = At4[j*33 + ((2*tlB)   ^ swz)];
            float4 A1 = At4[j*33 + ((2*tlB+1) ^ swz)];
            float4 v0 = V4c[j*17 + 2*tmB];
            float4 v1 = V4c[j*17 + 2*tmB + 1];
            u64c ap[4] = { pk(A0.x,A0.y), pk(A0.z,A0.w),
                           pk(A1.x,A1.y), pk(A1.z,A1.w) };
            float vf[8] = {v0.x,v0.y,v0.z,v0.w, v1.x,v1.y,v1.z,v1.w};
            #pragma unroll
            for (int m = 0; m < 8; m++) {
                u64c vd = dupf(vf[m]);
                #pragma unroll
                for (int lp = 0; lp < 4; lp++)
                    oav[lp][m] = ffma2(ap[lp], vd, oav[lp][m]);
            }
        }
    } else if (tid < 256) {
        // qU: 8l x 8m, two passes (sin half, cos half) -> obuf overlay on kT
        float4* ob4 = (float4*)kT;           // [128 l][16 f4]
        const float4* U4c = (const float4*)U;
        #pragma unroll
        for (int pass = 0; pass < 2; pass++) {
            u64c ua[4][8];
            #pragma unroll
            for (int lp = 0; lp < 4; lp++)
                #pragma unroll
                for (int m = 0; m < 8; m++) ua[lp][m] = pk(0.f,0.f);
            const int uoff = pass ? 64*17 : 0;
            #pragma unroll 2
            for (int d = 0; d < 64; d++) {
                float4 qa = qT4[d*33 + 2*tlB];
                float4 qb = qT4[d*33 + 2*tlB + 1];
                float4 u0 = U4c[uoff + d*17 + 2*tmB];
                float4 u1 = U4c[uoff + d*17 + 2*tmB + 1];
                u64c qp[4] = { pk(qa.x,qa.y), pk(qa.z,qa.w),
                               pk(qb.x,qb.y), pk(qb.z,qb.w) };
                float uf[8] = {u0.x,u0.y,u0.z,u0.w, u1.x,u1.y,u1.z,u1.w};
                #pragma unroll
                for (int m = 0; m < 8; m++) {
                    u64c ud = dupf(uf[m]);
                    #pragma unroll
                    for (int lp = 0; lp < 4; lp++)
                        ua[lp][m] = ffma2(qp[lp], ud, ua[lp][m]);
                }
            }
            #pragma unroll
            for (int lp = 0; lp < 4; lp++) {
                int le = lB0 + 2*lp, lo_ = le + 1;
                float fE = pass ? cth[le]  : sth[le];
                float fO = pass ? cth[lo_] : sth[lo_];
                float2 m01 = up(ua[lp][0]), m23 = up(ua[lp][1]);
                float2 m45 = up(ua[lp][2]), m67 = up(ua[lp][3]);
                float2 n01 = up(ua[lp][4]), n23 = up(ua[lp][5]);
                float2 n45 = up(ua[lp][6]), n67 = up(ua[lp][7]);
                // m01.x = (l even, m 8tmB+0) ... layout: ua[lp][m], pairs over l.
                float4 e0 = make_float4(m01.x, m23.x, m45.x, m67.x);
                float4 e1 = make_float4(n01.x, n23.x, n45.x, n67.x);
                float4 o0 = make_float4(m01.y, m23.y, m45.y, m67.y);
                float4 o1 = make_float4(n01.y, n23.y, n45.y, n67.y);
                if (pass == 0) {
                    ob4[le*16  + 2*tmB]     = make_float4(e0.x*fE, e0.y*fE, e0.z*fE, e0.w*fE);
                    ob4[le*16  + 2*tmB + 1] = make_float4(e1.x*fE, e1.y*fE, e1.z*fE, e1.w*fE);
                    ob4[lo_*16 + 2*tmB]     = make_float4(o0.x*fO, o0.y*fO, o0.z*fO, o0.w*fO);
                    ob4[lo_*16 + 2*tmB + 1] = make_float4(o1.x*fO, o1.y*fO, o1.z*fO, o1.w*fO);
                } else {
                    float4 t0 = ob4[le*16  + 2*tmB];
                    float4 t1 = ob4[le*16  + 2*tmB + 1];
                    float4 t2 = ob4[lo_*16 + 2*tmB];
                    float4 t3 = ob4[lo_*16 + 2*tmB + 1];
                    ob4[le*16  + 2*tmB]     = make_float4(fmaf(e0.x,fE,t0.x), fmaf(e0.y,fE,t0.y), fmaf(e0.z,fE,t0.z), fmaf(e0.w,fE,t0.w));
                    ob4[le*16  + 2*tmB + 1] = make_float4(fmaf(e1.x,fE,t1.x), fmaf(e1.y,fE,t1.y), fmaf(e1.z,fE,t1.z), fmaf(e1.w,fE,t1.w));
                    ob4[lo_*16 + 2*tmB]     = make_float4(fmaf(o0.x,fO,t2.x), fmaf(o0.y,fO,t2.y), fmaf(o0.z,fO,t2.z), fmaf(o0.w,fO,t2.w));
                    ob4[lo_*16 + 2*tmB + 1] = make_float4(fmaf(o1.x,fO,t3.x), fmaf(o1.y,fO,t3.y), fmaf(o1.z,fO,t3.z), fmaf(o1.w,fO,t3.w));
                }
            }
        }
    } else {
        // Denominator: 256 threads, 2 partials per l
        const int t2 = tid - 256;
        const int l = t2 >> 1, part = t2 & 1;
        float dd = 0.f;
        const int jlo = part*64;
        const int jhi = min(jlo + 64, l + 1);
        for (int j = jlo; j < jhi; j++) {
            int swz = (j >> 3) & 7;
            dd += kx[j*132 + 4*((l>>2) ^ swz) + (l & 3)];
        }
        const float sl_ = sth[l], cl_ = cth[l];
        const int dlo = part*32;
        #pragma unroll 8
        for (int d = dlo; d < dlo + 32; d++)
            dd = fmaf(qT[d*132 + l], fmaf(sl_, zext[d], cl_*zext[d+64]), dd);
        dscr[t2] = dd;
    }
    __syncthreads();

    // ---- Combine + divide + store (wid 0..3, oav in registers) ----
    if (tid < 128) {
        const float4* ob4 = (const float4*)kT;
        float* ob = out + base;
        #pragma unroll
        for (int lp = 0; lp < 4; lp++) {
            int le = lB0 + 2*lp, lo_ = le + 1;
            float r0 = 1.f / fmaxf(dscr[2*le]  + dscr[2*le+1],  1e-6f);
            float r1 = 1.f / fmaxf(dscr[2*lo_] + dscr[2*lo_+1], 1e-6f);
            float4 qe0 = ob4[le*16  + 2*tmB];
            float4 qe1 = ob4[le*16  + 2*tmB + 1];
            float4 qo0 = ob4[lo_*16 + 2*tmB];
            float4 qo1 = ob4[lo_*16 + 2*tmB + 1];
            float2 a0 = up(oav[lp][0]), a1 = up(oav[lp][1]);
            float2 a2_ = up(oav[lp][2]), a3 = up(oav[lp][3]);
            float2 a4 = up(oav[lp][4]), a5 = up(oav[lp][5]);
            float2 a6 = up(oav[lp][6]), a7 = up(oav[lp][7]);
            *(float4*)&ob[le*64 + 8*tmB] =
                make_float4((a0.x+qe0.x)*r0, (a1.x+qe0.y)*r0, (a2_.x+qe0.z)*r0, (a3.x+qe0.w)*r0);
            *(float4*)&ob[le*64 + 8*tmB + 4] =
                make_float4((a4.x+qe1.x)*r0, (a5.x+qe1.y)*r0, (a6.x+qe1.z)*r0, (a7.x+qe1.w)*r0);
            *(float4*)&ob[lo_*64 + 8*tmB] =
                make_float4((a0.y+qo0.x)*r1, (a1.y+qo0.y)*r1, (a2_.y+qo0.z)*r1, (a3.y+qo0.w)*r1);
            *(float4*)&ob[lo_*64 + 8*tmB + 4] =
                make_float4((a4.y+qo1.x)*r1, (a5.y+qo1.y)*r1, (a6.y+qo1.z)*r1, (a7.y+qo1.w)*r1);
        }
    }
}

extern "C" void kernel_launch(void* const* d_in, const int* in_sizes, int n_in,
                              void* d_out, int out_size) {
    const float* q = (const float*)d_in[0];
    const float* k = (const float*)d_in[1];
    const float* v = (const float*)d_in[2];
    float* out = (float*)d_out;

    const int smem = (64*132 + 64*132 + 128*132 + 32 + 2*128*68 + 3*128 + 256) * 4; // 208,512 B
    cudaFuncSetAttribute(fused_cos_attn, cudaFuncAttributeMaxDynamicSharedMemorySize, smem);
    fused_cos_attn<<<NBLK, 512, smem>>>(q, k, v, out);
}

// round 15
// speedup vs baseline: 1.3821x; 1.3821x over previous
#include <cuda_runtime.h>
#include <string.h>

#define NSEQ 16          // B*H
#define SEQL 1024        // L
#define DIM  64          // D
#define CHK  128         // chunk size
#define NCHK 8
#define D2   128         // 2*DIM
#define NBLK 128

// smem strides (floats) chosen for conflict-free MMA fragment loads
#define QX_S 132
#define KX_S 136
#define V_S  72
#define U_S  72

__device__ float g_S[NSEQ*NCHK*D2*DIM];
__device__ float g_z[NSEQ*NCHK*D2];
__device__ unsigned int g_bar;   // zero-init; monotone across replays

__device__ __forceinline__ float4 relu4(float4 a){
    a.x = fmaxf(a.x,0.f); a.y = fmaxf(a.y,0.f);
    a.z = fmaxf(a.z,0.f); a.w = fmaxf(a.w,0.f);
    return a;
}
// round-to-nearest tf32 (kept in a float container)
__device__ __forceinline__ float tff(float x){
    unsigned u; asm("cvt.rna.tf32.f32 %0, %1;" : "=r"(u) : "f"(x));
    return __uint_as_float(u);
}
// D += A*B, m16n8k8 tf32
__device__ __forceinline__ void mma8(float* d, const float* a, const float* b){
    asm volatile(
        "mma.sync.aligned.m16n8k8.row.col.f32.tf32.tf32.f32 "
        "{%0,%1,%2,%3},{%4,%5,%6,%7},{%8,%9},{%0,%1,%2,%3};"
        : "+f"(d[0]), "+f"(d[1]), "+f"(d[2]), "+f"(d[3])
        : "r"(__float_as_uint(a[0])), "r"(__float_as_uint(a[1])),
          "r"(__float_as_uint(a[2])), "r"(__float_as_uint(a[3])),
          "r"(__float_as_uint(b[0])), "r"(__float_as_uint(b[1])));
}
// A fragment (row-major M16xK8 tile at (r0,c0), stride S)
__device__ __forceinline__ void lda(float* a, const float* buf, int r0, int c0,
                                    int S, int row, int col){
    a[0] = buf[(r0+row)*S   + c0+col];
    a[1] = buf[(r0+row+8)*S + c0+col];
    a[2] = buf[(r0+row)*S   + c0+col+4];
    a[3] = buf[(r0+row+8)*S + c0+col+4];
}
// B fragment (K8xN8 tile at (k0,n0), row-major [k][n] buffer, stride S)
__device__ __forceinline__ void ldb(float* b, const float* buf, int k0, int n0,
                                    int S, int row, int col){
    b[0] = buf[(k0+col)*S   + n0+row];
    b[1] = buf[(k0+col+4)*S + n0+row];
}

__device__ __forceinline__ void grid_barrier() {
    __threadfence();
    __syncthreads();
    if (threadIdx.x == 0) {
        unsigned gen = atomicAdd(&g_bar, 1u);
        unsigned target = (gen / NBLK + 1u) * NBLK;
        while (atomicAdd(&g_bar, 0u) < target) { }
    }
    __syncthreads();
    __threadfence();
}

// ---------------------------------------------------------------------------
// Fused tf32-MMA kernel. grid = 128, block = 512.
// ---------------------------------------------------------------------------
__global__ void __launch_bounds__(512,1)
fused_cos_attn(const float* __restrict__ q, const float* __restrict__ k,
               const float* __restrict__ v, float* __restrict__ out) {
    const int blk = blockIdx.x;
    const int n = blk >> 3, c = blk & 7;
    extern __shared__ float sm[];
    float* Qx   = sm;                    // [128 l][132]  qext (tf32) row-major
    float* kxT  = Qx + 128*QX_S;         // [128 d'][136] kext^T (tf32); A-buf overlay
    float* V    = kxT + 128*KX_S;        // [128 j][72]   relu(v) (tf32)
    float* U    = V + 128*V_S;           // [128 d'][72]  prefix state (tf32)
    float* sth  = U + 128*U_S;           // 128
    float* cth  = sth + 128;             // 128
    float* zext = cth + 128;             // 128 (fp32 prefix z)
    float* den  = zext + 128;            // 128 (reciprocal denominators)
    float* dscr = den + 128;             // 256 (A row-sum partials)
    float* dscr2= dscr + 256;            // 128 (inter-term partials)

    const int tid  = threadIdx.x;
    const int lane = tid & 31, wid = tid >> 5;
    const int row  = lane >> 2, qcol = lane & 3;
    const size_t base = ((size_t)n*SEQL + (size_t)c*CHK)*DIM;
    const float4* q4 = (const float4*)(q + base);
    const float4* k4 = (const float4*)(k + base);
    const float4* v4 = (const float4*)(v + base);

    // ---- Stage (tf32-rounded): Qx=[l][d'], kxT=[d'][j], V=[j][m] ----
    {
        const int j = tid & 127;
        const float ang = 1.5707963268f * (float)(c*CHK + j + 1) * (1.f/(float)SEQL);
        const float s = __sinf(ang), cc = __cosf(ang);
        if (tid < 128) { sth[j] = s; cth[j] = cc; }
        #pragma unroll
        for (int it = 0; it < 4; it++) {
            int f = (tid >> 7) + 4*it;       // 0..15
            int d = 4*f;
            float4 qq = relu4(q4[j*16 + f]);
            float4 kk = relu4(k4[j*16 + f]);
            float4 vv = relu4(v4[j*16 + f]);
            *(float4*)&Qx[j*QX_S + d] =
                make_float4(tff(qq.x*s), tff(qq.y*s), tff(qq.z*s), tff(qq.w*s));
            *(float4*)&Qx[j*QX_S + 64 + d] =
                make_float4(tff(qq.x*cc), tff(qq.y*cc), tff(qq.z*cc), tff(qq.w*cc));
            kxT[(d+0)*KX_S + j] = tff(kk.x*s);  kxT[(d+64)*KX_S + j] = tff(kk.x*cc);
            kxT[(d+1)*KX_S + j] = tff(kk.y*s);  kxT[(d+65)*KX_S + j] = tff(kk.y*cc);
            kxT[(d+2)*KX_S + j] = tff(kk.z*s);  kxT[(d+66)*KX_S + j] = tff(kk.z*cc);
            kxT[(d+3)*KX_S + j] = tff(kk.w*s);  kxT[(d+67)*KX_S + j] = tff(kk.w*cc);
            *(float4*)&V[j*V_S + d] =
                make_float4(tff(vv.x), tff(vv.y), tff(vv.z), tff(vv.w));
        }
    }
    __syncthreads();

    // ---- Chunk-state GEMM (warps 0..7): S[d'][m] = sum_j kxT[d'][j]*V[j][m] ----
    if (wid < 8) {
        const int r0 = wid*16;
        float acc[8][4];
        #pragma unroll
        for (int nt = 0; nt < 8; nt++)
            #pragma unroll
            for (int i = 0; i < 4; i++) acc[nt][i] = 0.f;
        #pragma unroll 4
        for (int kt = 0; kt < 16; kt++) {
            float a[4]; lda(a, kxT, r0, 8*kt, KX_S, row, qcol);
            #pragma unroll
            for (int nt = 0; nt < 8; nt++) {
                float b[2]; ldb(b, V, 8*kt, 8*nt, V_S, row, qcol);
                mma8(acc[nt], a, b);
            }
        }
        float* oS = g_S + (size_t)blk*D2*DIM;
        #pragma unroll
        for (int nt = 0; nt < 8; nt++) {
            int colb = 8*nt + 2*qcol;
            *(float2*)&oS[(r0+row)*64 + colb]   = make_float2(acc[nt][0], acc[nt][1]);
            *(float2*)&oS[(r0+row+8)*64 + colb] = make_float2(acc[nt][2], acc[nt][3]);
        }
    } else if (tid < 384) {
        // z[d'] = row sums of kxT
        const int dp = tid - 256;
        const float4* r4 = (const float4*)&kxT[dp*KX_S];
        float zz = 0.f;
        #pragma unroll 8
        for (int g = 0; g < 32; g++) {
            float4 t = r4[g];
            zz += t.x + t.y + t.z + t.w;
        }
        g_z[blk*D2 + dp] = zz;
    }

    grid_barrier();

    // ---- Phase A (warps 0..11, SMSP-balanced LUT) || U/zext prefix (12..15) --
    const bool actA = (wid < 12);
    int lg = 0, jh = 0, ntc = 0;
    float accA[8][4];
    if (actA) {
        lg = (wid < 8) ? (int)((0x75436210u >> (4*wid)) & 15u)
                       : (int)((0x4567u >> (4*(wid-8))) & 15u);
        jh = (wid >= 8) ? 1 : 0;
        ntc = (16*lg + 15 - 64*jh) / 8 + 1;
        if (ntc > 8) ntc = 8;
        #pragma unroll
        for (int nt = 0; nt < 8; nt++)
            #pragma unroll
            for (int i = 0; i < 4; i++) accA[nt][i] = 0.f;
        #pragma unroll 2
        for (int kt = 0; kt < 16; kt++) {
            float a[4]; lda(a, Qx, 16*lg, 8*kt, QX_S, row, qcol);
            #pragma unroll
            for (int nt = 0; nt < 8; nt++) {
                if (nt < ntc) {
                    float b[2]; ldb(b, kxT, 8*kt, 64*jh + 8*nt, KX_S, row, qcol);
                    mma8(accA[nt], a, b);
                }
            }
        }
    } else {
        const int t = tid - 384;                // 0..127
        dscr[t] = 0.f; dscr[t+128] = 0.f;
        const float4* gSn = (const float4*)(g_S + (size_t)(n*NCHK)*D2*DIM);
        #pragma unroll 2
        for (int it = 0; it < 16; it++) {
            int idx = t + 128*it;               // 0..2047
            int r_ = idx >> 4, g = idx & 15;
            float4 acc = make_float4(0.f,0.f,0.f,0.f);
            for (int cc = 0; cc < c; cc++) {
                float4 x = gSn[(size_t)cc*2048 + idx];
                acc.x += x.x; acc.y += x.y; acc.z += x.z; acc.w += x.w;
            }
            *(float4*)&U[r_*U_S + 4*g] =
                make_float4(tff(acc.x), tff(acc.y), tff(acc.z), tff(acc.w));
        }
        float zz = 0.f;
        for (int cc = 0; cc < c; cc++) zz += g_z[(n*NCHK + cc)*D2 + t];
        zext[t] = zz;
    }
    __syncthreads();

    // ---- Phase A epilogue: mask, tf32, store A over kxT; row-sum partials ----
    // Concurrently warps 12..15 compute inter-term partials dscr2.
    if (actA) {
        const int l_lo = 16*lg + row, l_hi = l_lo + 8;
        float slo = 0.f, shi = 0.f;
        #pragma unroll
        for (int nt = 0; nt < 8; nt++) {
            if (nt < ntc) {
                int jc = 64*jh + 8*nt + 2*qcol;
                float w0 = (jc   <= l_lo) ? accA[nt][0] : 0.f;
                float w1 = (jc+1 <= l_lo) ? accA[nt][1] : 0.f;
                float w2 = (jc   <= l_hi) ? accA[nt][2] : 0.f;
                float w3 = (jc+1 <= l_hi) ? accA[nt][3] : 0.f;
                slo += w0 + w1;  shi += w2 + w3;
                *(float2*)&kxT[l_lo*KX_S + jc] = make_float2(tff(w0), tff(w1));
                *(float2*)&kxT[l_hi*KX_S + jc] = make_float2(tff(w2), tff(w3));
            }
        }
        slo += __shfl_xor_sync(0xffffffffu, slo, 1);
        slo += __shfl_xor_sync(0xffffffffu, slo, 2);
        shi += __shfl_xor_sync(0xffffffffu, shi, 1);
        shi += __shfl_xor_sync(0xffffffffu, shi, 2);
        if (qcol == 0) {
            dscr[2*l_lo + jh] = slo;
            dscr[2*l_hi + jh] = shi;
        }
    } else {
        const int l = tid - 384;                // 0..127
        float s = 0.f;
        #pragma unroll 4
        for (int i = 0; i < 32; i++) {
            float4 qv = *(const float4*)&Qx[l*QX_S + 4*i];
            float4 zv = *(const float4*)&zext[4*i];
            s = fmaf(qv.x, zv.x, s); s = fmaf(qv.y, zv.y, s);
            s = fmaf(qv.z, zv.z, s); s = fmaf(qv.w, zv.w, s);
        }
        dscr2[l] = s;
    }
    __syncthreads();

    if (tid < 128) {
        float dd = dscr[2*tid] + dscr[2*tid+1] + dscr2[tid];
        den[tid] = 1.f / fmaxf(dd, 1e-6f);
    }
    __syncthreads();

    // ---- AV (causal) + qU fused into one accumulator (16 warps) ----
    {
        const int lg2 = wid >> 1, mg = wid & 1;
        const int ktmax = 2*lg2 + 2;
        float acc[4][4];
        #pragma unroll
        for (int nt = 0; nt < 4; nt++)
            #pragma unroll
            for (int i = 0; i < 4; i++) acc[nt][i] = 0.f;

        // AV: A (masked, tf32) over kxT area, B = V
        #pragma unroll 2
        for (int kt = 0; kt < 16; kt++) {
            if (kt < ktmax) {
                float a[4]; lda(a, kxT, 16*lg2, 8*kt, KX_S, row, qcol);
                #pragma unroll
                for (int nt = 0; nt < 4; nt++) {
                    float b[2]; ldb(b, V, 8*kt, 32*mg + 8*nt, V_S, row, qcol);
                    mma8(acc[nt], a, b);
                }
            }
        }
        // qU: A = Qx (d' = 0..127), B = U
        #pragma unroll 2
        for (int kt = 0; kt < 16; kt++) {
            float a[4]; lda(a, Qx, 16*lg2, 8*kt, QX_S, row, qcol);
            #pragma unroll
            for (int nt = 0; nt < 4; nt++) {
                float b[2]; ldb(b, U, 8*kt, 32*mg + 8*nt, U_S, row, qcol);
                mma8(acc[nt], a, b);
            }
        }

        const int l_lo = 16*lg2 + row, l_hi = l_lo + 8;
        const float rlo = den[l_lo], rhi = den[l_hi];
        float* ob = out + base;
        #pragma unroll
        for (int nt = 0; nt < 4; nt++) {
            int colb = 32*mg + 8*nt + 2*qcol;
            *(float2*)&ob[l_lo*64 + colb] = make_float2(acc[nt][0]*rlo, acc[nt][1]*rlo);
            *(float2*)&ob[l_hi*64 + colb] = make_float2(acc[nt][2]*rhi, acc[nt][3]*rhi);
        }
    }
}

extern "C" void kernel_launch(void* const* d_in, const int* in_sizes, int n_in,
                              void* d_out, int out_size) {
    const float* q = (const float*)d_in[0];
    const float* k = (const float*)d_in[1];
    const float* v = (const float*)d_in[2];
    float* out = (float*)d_out;

    const int smem = (128*QX_S + 128*KX_S + 128*V_S + 128*U_S
                      + 128 + 128 + 128 + 128 + 256 + 128) * 4;   // 214,528 B
    cudaFuncSetAttribute(fused_cos_attn, cudaFuncAttributeMaxDynamicSharedMemorySize, smem);
    fused_cos_attn<<<NBLK, 512, smem>>>(q, k, v, out);
}

// round 16
// speedup vs baseline: 1.3934x; 1.0082x over previous
#include <cuda_runtime.h>
#include <string.h>

#define NSEQ 16          // B*H
#define SEQL 1024        // L
#define DIM  64          // D
#define CHK  128         // chunk size
#define NCHK 8
#define D2   128         // 2*DIM
#define NBLK 128

// smem strides (floats) chosen for conflict-free MMA fragment loads
#define QX_S 132
#define KX_S 136
#define V_S  72
#define U_S  72

__device__ float g_S[NSEQ*NCHK*D2*DIM];
__device__ float g_z[NSEQ*NCHK*D2];
__device__ unsigned int g_bar;   // zero-init; monotone across replays

__device__ __forceinline__ float4 relu4(float4 a){
    a.x = fmaxf(a.x,0.f); a.y = fmaxf(a.y,0.f);
    a.z = fmaxf(a.z,0.f); a.w = fmaxf(a.w,0.f);
    return a;
}
__device__ __forceinline__ float tff(float x){
    unsigned u; asm("cvt.rna.tf32.f32 %0, %1;" : "=r"(u) : "f"(x));
    return __uint_as_float(u);
}
// D += A*B, m16n8k8 tf32
__device__ __forceinline__ void mma8(float* d, const float* a, const float* b){
    asm volatile(
        "mma.sync.aligned.m16n8k8.row.col.f32.tf32.tf32.f32 "
        "{%0,%1,%2,%3},{%4,%5,%6,%7},{%8,%9},{%0,%1,%2,%3};"
        : "+f"(d[0]), "+f"(d[1]), "+f"(d[2]), "+f"(d[3])
        : "r"(__float_as_uint(a[0])), "r"(__float_as_uint(a[1])),
          "r"(__float_as_uint(a[2])), "r"(__float_as_uint(a[3])),
          "r"(__float_as_uint(b[0])), "r"(__float_as_uint(b[1])));
}
// A fragment (row-major M16xK8 tile at (r0,c0), stride S)
__device__ __forceinline__ void lda(float* a, const float* buf, int r0, int c0,
                                    int S, int row, int col){
    a[0] = buf[(r0+row)*S   + c0+col];
    a[1] = buf[(r0+row+8)*S + c0+col];
    a[2] = buf[(r0+row)*S   + c0+col+4];
    a[3] = buf[(r0+row+8)*S + c0+col+4];
}
// B fragment (K8xN8 tile at (k0,n0), row-major [k][n] buffer, stride S)
__device__ __forceinline__ void ldb(float* b, const float* buf, int k0, int n0,
                                    int S, int row, int col){
    b[0] = buf[(k0+col)*S   + n0+row];
    b[1] = buf[(k0+col+4)*S + n0+row];
}

__device__ __forceinline__ void grid_barrier() {
    __threadfence();
    __syncthreads();
    if (threadIdx.x == 0) {
        unsigned gen = atomicAdd(&g_bar, 1u);
        unsigned target = (gen / NBLK + 1u) * NBLK;
        while (atomicAdd(&g_bar, 0u) < target) { }
    }
    __syncthreads();
    __threadfence();
}

// ---------------------------------------------------------------------------
// Fused tf32-MMA kernel. grid = 128, block = 512.
// ---------------------------------------------------------------------------
__global__ void __launch_bounds__(512,1)
fused_cos_attn(const float* __restrict__ q, const float* __restrict__ k,
               const float* __restrict__ v, float* __restrict__ out) {
    const int blk = blockIdx.x;
    const int n = blk >> 3, c = blk & 7;
    extern __shared__ float sm[];
    float* Qx   = sm;                    // [128 l][132]  qext (tf32) row-major
    float* kxT  = Qx + 128*QX_S;         // [128 d'][136] kext^T (tf32); A-buf overlay
    float* V    = kxT + 128*KX_S;        // [128 j][72]   relu(v) + ones col 64
    float* U    = V + 128*V_S;           // [128 d'][72]  prefix state (tf32)
    float* sth  = U + 128*U_S;           // 128
    float* cth  = sth + 128;             // 128
    float* zext = cth + 128;             // 128 (fp32 prefix z)
    float* den  = zext + 128;            // 128 (reciprocal denominators)
    float* dscr = den + 128;             // 256 (A row-sum partials)
    float* dscr2= dscr + 256;            // 128 (inter-term partials)

    const int tid  = threadIdx.x;
    const int lane = tid & 31, wid = tid >> 5;
    const int row  = lane >> 2, qcol = lane & 3;
    const size_t base = ((size_t)n*SEQL + (size_t)c*CHK)*DIM;
    const float4* q4 = (const float4*)(q + base);
    const float4* k4 = (const float4*)(k + base);
    const float4* v4 = (const float4*)(v + base);

    // ---- Stage (tf32-rounded): Qx=[l][d'], kxT=[d'][j], V=[j][m] + ones ----
    {
        const int j = tid & 127;
        const float ang = 1.5707963268f * (float)(c*CHK + j + 1) * (1.f/(float)SEQL);
        const float s = __sinf(ang), cc = __cosf(ang);
        if (tid < 128) {
            sth[j] = s; cth[j] = cc;
            *(float4*)&V[j*V_S + 64] = make_float4(1.f, 0.f, 0.f, 0.f);
            *(float4*)&V[j*V_S + 68] = make_float4(0.f, 0.f, 0.f, 0.f);
        }
        #pragma unroll
        for (int it = 0; it < 4; it++) {
            int f = (tid >> 7) + 4*it;       // 0..15
            int d = 4*f;
            float4 qq = relu4(q4[j*16 + f]);
            float4 kk = relu4(k4[j*16 + f]);
            float4 vv = relu4(v4[j*16 + f]);
            *(float4*)&Qx[j*QX_S + d] =
                make_float4(tff(qq.x*s), tff(qq.y*s), tff(qq.z*s), tff(qq.w*s));
            *(float4*)&Qx[j*QX_S + 64 + d] =
                make_float4(tff(qq.x*cc), tff(qq.y*cc), tff(qq.z*cc), tff(qq.w*cc));
            kxT[(d+0)*KX_S + j] = tff(kk.x*s);  kxT[(d+64)*KX_S + j] = tff(kk.x*cc);
            kxT[(d+1)*KX_S + j] = tff(kk.y*s);  kxT[(d+65)*KX_S + j] = tff(kk.y*cc);
            kxT[(d+2)*KX_S + j] = tff(kk.z*s);  kxT[(d+66)*KX_S + j] = tff(kk.z*cc);
            kxT[(d+3)*KX_S + j] = tff(kk.w*s);  kxT[(d+67)*KX_S + j] = tff(kk.w*cc);
            *(float4*)&V[j*V_S + d] =
                make_float4(tff(vv.x), tff(vv.y), tff(vv.z), tff(vv.w));
        }
    }
    __syncthreads();

    // ---- Chunk-state GEMM (ALL 16 warps): S[d'][m] = sum_j kxT[d'][j]*V[j][m]
    //      plus z via ones-column (nt=8, col 64). warp -> (rt, nh) SMSP-balanced.
    {
        const int rt = wid >> 1;
        const int nh = (wid & 1) ^ ((wid >> 2) & 1);   // bijective with rt
        const int r0 = rt*16;
        const int NT = nh ? 5 : 4;                     // nh=1 also covers ones col
        float acc[5][4];
        #pragma unroll
        for (int i = 0; i < 5; i++)
            #pragma unroll
            for (int t = 0; t < 4; t++) acc[i][t] = 0.f;
        #pragma unroll 4
        for (int kt = 0; kt < 16; kt++) {
            float a[4]; lda(a, kxT, r0, 8*kt, KX_S, row, qcol);
            #pragma unroll
            for (int i = 0; i < 5; i++) {
                if (i < NT) {
                    int nt = nh ? (4 + i) : i;
                    float b[2]; ldb(b, V, 8*kt, 8*nt, V_S, row, qcol);
                    mma8(acc[i], a, b);
                }
            }
        }
        float* oS = g_S + (size_t)blk*D2*DIM;
        #pragma unroll
        for (int i = 0; i < 4; i++) {
            int nt = nh ? (4 + i) : i;
            int colb = 8*nt + 2*qcol;
            *(float2*)&oS[(r0+row)*64 + colb]   = make_float2(acc[i][0], acc[i][1]);
            *(float2*)&oS[(r0+row+8)*64 + colb] = make_float2(acc[i][2], acc[i][3]);
        }
        if (nh && qcol == 0) {                         // z from ones column (col 64)
            g_z[blk*D2 + r0 + row]     = acc[4][0];
            g_z[blk*D2 + r0 + row + 8] = acc[4][2];
        }
    }

    grid_barrier();

    // ---- Phase A (warps 0..11, SMSP-balanced LUT) || U/zext prefix (12..15) --
    const bool actA = (wid < 12);
    int lg = 0, jh = 0, ntc = 0;
    float accA[8][4];
    if (actA) {
        lg = (wid < 8) ? (int)((0x75436210u >> (4*wid)) & 15u)
                       : (int)((0x4567u >> (4*(wid-8))) & 15u);
        jh = (wid >= 8) ? 1 : 0;
        ntc = (16*lg + 15 - 64*jh) / 8 + 1;
        if (ntc > 8) ntc = 8;
        #pragma unroll
        for (int nt = 0; nt < 8; nt++)
            #pragma unroll
            for (int i = 0; i < 4; i++) accA[nt][i] = 0.f;
        #pragma unroll 2
        for (int kt = 0; kt < 16; kt++) {
            float a[4]; lda(a, Qx, 16*lg, 8*kt, QX_S, row, qcol);
            #pragma unroll
            for (int nt = 0; nt < 8; nt++) {
                if (nt < ntc) {
                    float b[2]; ldb(b, kxT, 8*kt, 64*jh + 8*nt, KX_S, row, qcol);
                    mma8(accA[nt], a, b);
                }
            }
        }
    } else {
        const int t = tid - 384;                // 0..127
        dscr[t] = 0.f; dscr[t+128] = 0.f;
        const float4* gSn = (const float4*)(g_S + (size_t)(n*NCHK)*D2*DIM);
        #pragma unroll 2
        for (int it = 0; it < 16; it++) {
            int idx = t + 128*it;               // 0..2047
            int r_ = idx >> 4, g = idx & 15;
            float4 acc = make_float4(0.f,0.f,0.f,0.f);
            for (int cc = 0; cc < c; cc++) {
                float4 x = gSn[(size_t)cc*2048 + idx];
                acc.x += x.x; acc.y += x.y; acc.z += x.z; acc.w += x.w;
            }
            *(float4*)&U[r_*U_S + 4*g] =
                make_float4(tff(acc.x), tff(acc.y), tff(acc.z), tff(acc.w));
        }
        float zz = 0.f;
        for (int cc = 0; cc < c; cc++) zz += g_z[(n*NCHK + cc)*D2 + t];
        zext[t] = zz;
    }
    __syncthreads();

    // ---- Phase A epilogue: mask, tf32, store A over kxT; row-sum partials ----
    if (actA) {
        const int l_lo = 16*lg + row, l_hi = l_lo + 8;
        float slo = 0.f, shi = 0.f;
        #pragma unroll
        for (int nt = 0; nt < 8; nt++) {
            if (nt < ntc) {
                int jc = 64*jh + 8*nt + 2*qcol;
                float w0 = (jc   <= l_lo) ? accA[nt][0] : 0.f;
                float w1 = (jc+1 <= l_lo) ? accA[nt][1] : 0.f;
                float w2 = (jc   <= l_hi) ? accA[nt][2] : 0.f;
                float w3 = (jc+1 <= l_hi) ? accA[nt][3] : 0.f;
                slo += w0 + w1;  shi += w2 + w3;
                *(float2*)&kxT[l_lo*KX_S + jc] = make_float2(tff(w0), tff(w1));
                *(float2*)&kxT[l_hi*KX_S + jc] = make_float2(tff(w2), tff(w3));
            }
        }
        slo += __shfl_xor_sync(0xffffffffu, slo, 1);
        slo += __shfl_xor_sync(0xffffffffu, slo, 2);
        shi += __shfl_xor_sync(0xffffffffu, shi, 1);
        shi += __shfl_xor_sync(0xffffffffu, shi, 2);
        if (qcol == 0) {
            dscr[2*l_lo + jh] = slo;
            dscr[2*l_hi + jh] = shi;
        }
    } else {
        const int l = tid - 384;                // 0..127
        float s = 0.f;
        #pragma unroll 4
        for (int i = 0; i < 32; i++) {
            float4 qv = *(const float4*)&Qx[l*QX_S + 4*i];
            float4 zv = *(const float4*)&zext[4*i];
            s = fmaf(qv.x, zv.x, s); s = fmaf(qv.y, zv.y, s);
            s = fmaf(qv.z, zv.z, s); s = fmaf(qv.w, zv.w, s);
        }
        dscr2[l] = s;
    }
    __syncthreads();

    if (tid < 128) {
        float dd = dscr[2*tid] + dscr[2*tid+1] + dscr2[tid];
        den[tid] = 1.f / fmaxf(dd, 1e-6f);
    }
    __syncthreads();

    // ---- AV (causal) + qU fused (16 warps, SMSP-balanced l-tile map) ----
    {
        const int smsp = wid & 3;
        const int lg2 = ((wid >> 2) & 1) ? (7 - smsp) : smsp;
        const int mg  = wid >> 3;
        const int ktmax = 2*lg2 + 2;
        float acc[4][4];
        #pragma unroll
        for (int nt = 0; nt < 4; nt++)
            #pragma unroll
            for (int i = 0; i < 4; i++) acc[nt][i] = 0.f;

        // AV: A (masked, tf32) over kxT area, B = V
        #pragma unroll 2
        for (int kt = 0; kt < 16; kt++) {
            if (kt < ktmax) {
                float a[4]; lda(a, kxT, 16*lg2, 8*kt, KX_S, row, qcol);
                #pragma unroll
                for (int nt = 0; nt < 4; nt++) {
                    float b[2]; ldb(b, V, 8*kt, 32*mg + 8*nt, V_S, row, qcol);
                    mma8(acc[nt], a, b);
                }
            }
        }
        // qU: A = Qx (d' = 0..127), B = U
        #pragma unroll 2
        for (int kt = 0; kt < 16; kt++) {
            float a[4]; lda(a, Qx, 16*lg2, 8*kt, QX_S, row, qcol);
            #pragma unroll
            for (int nt = 0; nt < 4; nt++) {
                float b[2]; ldb(b, U, 8*kt, 32*mg + 8*nt, U_S, row, qcol);
                mma8(acc[nt], a, b);
            }
        }

        const int l_lo = 16*lg2 + row, l_hi = l_lo + 8;
        const float rlo = den[l_lo], rhi = den[l_hi];
        float* ob = out + base;
        #pragma unroll
        for (int nt = 0; nt < 4; nt++) {
            int colb = 32*mg + 8*nt + 2*qcol;
            *(float2*)&ob[l_lo*64 + colb] = make_float2(acc[nt][0]*rlo, acc[nt][1]*rlo);
            *(float2*)&ob[l_hi*64 + colb] = make_float2(acc[nt][2]*rhi, acc[nt][3]*rhi);
        }
    }
}

extern "C" void kernel_launch(void* const* d_in, const int* in_sizes, int n_in,
                              void* d_out, int out_size) {
    const float* q = (const float*)d_in[0];
    const float* k = (const float*)d_in[1];
    const float* v = (const float*)d_in[2];
    float* out = (float*)d_out;

    const int smem = (128*QX_S + 128*KX_S + 128*V_S + 128*U_S
                      + 128 + 128 + 128 + 128 + 256 + 128) * 4;   // 214,528 B
    cudaFuncSetAttribute(fused_cos_attn, cudaFuncAttributeMaxDynamicSharedMemorySize, smem);
    fused_cos_attn<<<NBLK, 512, smem>>>(q, k, v, out);
}

// round 17
// speedup vs baseline: 1.3949x; 1.0010x over previous
#include <cuda_runtime.h>
#include <string.h>

#define NSEQ 16          // B*H
#define SEQL 1024        // L
#define DIM  64          // D
#define CHK  128         // chunk size
#define NCHK 8
#define D2   128         // 2*DIM
#define NBLK 128

// smem strides (floats) chosen for conflict-free MMA fragment loads
#define QX_S 132
#define KX_S 136
#define V_S  72
#define U_S  72

__device__ float g_S[NSEQ*NCHK*D2*DIM];
__device__ float g_z[NSEQ*NCHK*D2];
__device__ unsigned int g_bar;   // zero-init; monotone across replays

__device__ __forceinline__ float4 relu4(float4 a){
    a.x = fmaxf(a.x,0.f); a.y = fmaxf(a.y,0.f);
    a.z = fmaxf(a.z,0.f); a.w = fmaxf(a.w,0.f);
    return a;
}
__device__ __forceinline__ float tff(float x){
    unsigned u; asm("cvt.rna.tf32.f32 %0, %1;" : "=r"(u) : "f"(x));
    return __uint_as_float(u);
}
// D += A*B, m16n8k8 tf32
__device__ __forceinline__ void mma8(float* d, const float* a, const float* b){
    asm volatile(
        "mma.sync.aligned.m16n8k8.row.col.f32.tf32.tf32.f32 "
        "{%0,%1,%2,%3},{%4,%5,%6,%7},{%8,%9},{%0,%1,%2,%3};"
        : "+f"(d[0]), "+f"(d[1]), "+f"(d[2]), "+f"(d[3])
        : "r"(__float_as_uint(a[0])), "r"(__float_as_uint(a[1])),
          "r"(__float_as_uint(a[2])), "r"(__float_as_uint(a[3])),
          "r"(__float_as_uint(b[0])), "r"(__float_as_uint(b[1])));
}
// A fragment (row-major M16xK8 tile at (r0,c0), stride S)
__device__ __forceinline__ void lda(float* a, const float* buf, int r0, int c0,
                                    int S, int row, int col){
    a[0] = buf[(r0+row)*S   + c0+col];
    a[1] = buf[(r0+row+8)*S + c0+col];
    a[2] = buf[(r0+row)*S   + c0+col+4];
    a[3] = buf[(r0+row+8)*S + c0+col+4];
}
// B fragment (K8xN8 tile at (k0,n0), row-major [k][n] buffer, stride S)
__device__ __forceinline__ void ldb(float* b, const float* buf, int k0, int n0,
                                    int S, int row, int col){
    b[0] = buf[(k0+col)*S   + n0+row];
    b[1] = buf[(k0+col+4)*S + n0+row];
}

__device__ __forceinline__ void grid_barrier() {
    __threadfence();
    __syncthreads();
    if (threadIdx.x == 0) {
        unsigned gen = atomicAdd(&g_bar, 1u);
        unsigned target = (gen / NBLK + 1u) * NBLK;
        while (atomicAdd(&g_bar, 0u) < target) { }
    }
    __syncthreads();
    __threadfence();
}

// ---------------------------------------------------------------------------
// Fused tf32-MMA kernel. grid = 128, block = 512.
// ---------------------------------------------------------------------------
__global__ void __launch_bounds__(512,1)
fused_cos_attn(const float* __restrict__ q, const float* __restrict__ k,
               const float* __restrict__ v, float* __restrict__ out) {
    const int blk = blockIdx.x;
    const int n = blk >> 3, c = blk & 7;
    extern __shared__ float sm[];
    float* Qx   = sm;                    // [128 l][132]  qext (tf32) row-major
    float* kxT  = Qx + 128*QX_S;         // [128 d'][136] kext^T (tf32); A-buf overlay
    float* V    = kxT + 128*KX_S;        // [128 j][72]   relu(v) + ones col 64
    float* U    = V + 128*V_S;           // [128 d'][72]  prefix state (tf32)
    float* sth  = U + 128*U_S;           // 128
    float* cth  = sth + 128;             // 128
    float* zext = cth + 128;             // 128 (fp32 prefix z)
    float* dscr = zext + 128;            // 256 (A row-sum partials)
    float* dscr2= dscr + 256;            // 128 (inter-term partials)

    const int tid  = threadIdx.x;
    const int lane = tid & 31, wid = tid >> 5;
    const int row  = lane >> 2, qcol = lane & 3;
    const size_t base = ((size_t)n*SEQL + (size_t)c*CHK)*DIM;
    const float4* q4 = (const float4*)(q + base);
    const float4* k4 = (const float4*)(k + base);
    const float4* v4 = (const float4*)(v + base);

    // ---- Stage (tf32-rounded): Qx=[l][d'], kxT=[d'][j], V=[j][m] + ones ----
    {
        const int j = tid & 127;
        const float ang = 1.5707963268f * (float)(c*CHK + j + 1) * (1.f/(float)SEQL);
        const float s = __sinf(ang), cc = __cosf(ang);
        if (tid < 128) {
            sth[j] = s; cth[j] = cc;
            *(float4*)&V[j*V_S + 64] = make_float4(1.f, 0.f, 0.f, 0.f);
            *(float4*)&V[j*V_S + 68] = make_float4(0.f, 0.f, 0.f, 0.f);
        }
        #pragma unroll
        for (int it = 0; it < 4; it++) {
            int f = (tid >> 7) + 4*it;       // 0..15
            int d = 4*f;
            float4 qq = relu4(q4[j*16 + f]);
            float4 kk = relu4(k4[j*16 + f]);
            float4 vv = relu4(v4[j*16 + f]);
            *(float4*)&Qx[j*QX_S + d] =
                make_float4(tff(qq.x*s), tff(qq.y*s), tff(qq.z*s), tff(qq.w*s));
            *(float4*)&Qx[j*QX_S + 64 + d] =
                make_float4(tff(qq.x*cc), tff(qq.y*cc), tff(qq.z*cc), tff(qq.w*cc));
            kxT[(d+0)*KX_S + j] = tff(kk.x*s);  kxT[(d+64)*KX_S + j] = tff(kk.x*cc);
            kxT[(d+1)*KX_S + j] = tff(kk.y*s);  kxT[(d+65)*KX_S + j] = tff(kk.y*cc);
            kxT[(d+2)*KX_S + j] = tff(kk.z*s);  kxT[(d+66)*KX_S + j] = tff(kk.z*cc);
            kxT[(d+3)*KX_S + j] = tff(kk.w*s);  kxT[(d+67)*KX_S + j] = tff(kk.w*cc);
            *(float4*)&V[j*V_S + d] =
                make_float4(tff(vv.x), tff(vv.y), tff(vv.z), tff(vv.w));
        }
    }
    __syncthreads();

    // ---- Chunk-state GEMM (ALL 16 warps): S[d'][m] = sum_j kxT[d'][j]*V[j][m]
    //      plus z via ones-column. Batched B loads + pipelined A loads. ----
    {
        const int rt = wid >> 1;
        const int nh = (wid & 1) ^ ((wid >> 2) & 1);
        const int r0 = rt*16;
        const int NT = nh ? 5 : 4;
        float acc[5][4];
        #pragma unroll
        for (int i = 0; i < 5; i++)
            #pragma unroll
            for (int t = 0; t < 4; t++) acc[i][t] = 0.f;

        float a[4]; lda(a, kxT, r0, 0, KX_S, row, qcol);
        #pragma unroll
        for (int kt = 0; kt < 16; kt++) {
            float b[5][2];
            #pragma unroll
            for (int i = 0; i < 5; i++) {
                if (i < NT) {
                    int nt = nh ? (4 + i) : i;
                    ldb(b[i], V, 8*kt, 8*nt, V_S, row, qcol);
                }
            }
            float an[4];
            if (kt < 15) lda(an, kxT, r0, 8*(kt+1), KX_S, row, qcol);
            #pragma unroll
            for (int i = 0; i < 5; i++)
                if (i < NT) mma8(acc[i], a, b[i]);
            if (kt < 15) { a[0]=an[0]; a[1]=an[1]; a[2]=an[2]; a[3]=an[3]; }
        }
        float* oS = g_S + (size_t)blk*D2*DIM;
        #pragma unroll
        for (int i = 0; i < 4; i++) {
            int nt = nh ? (4 + i) : i;
            int colb = 8*nt + 2*qcol;
            *(float2*)&oS[(r0+row)*64 + colb]   = make_float2(acc[i][0], acc[i][1]);
            *(float2*)&oS[(r0+row+8)*64 + colb] = make_float2(acc[i][2], acc[i][3]);
        }
        if (nh && qcol == 0) {
            g_z[blk*D2 + r0 + row]     = acc[4][0];
            g_z[blk*D2 + r0 + row + 8] = acc[4][2];
        }
    }

    grid_barrier();

    // ---- Phase A (warps 0..11, SMSP-balanced LUT) || U/zext prefix (12..15) --
    const bool actA = (wid < 12);
    int lg = 0, jh = 0, ntc = 0;
    float accA[8][4];
    if (actA) {
        lg = (wid < 8) ? (int)((0x75436210u >> (4*wid)) & 15u)
                       : (int)((0x4567u >> (4*(wid-8))) & 15u);
        jh = (wid >= 8) ? 1 : 0;
        ntc = (16*lg + 15 - 64*jh) / 8 + 1;
        if (ntc > 8) ntc = 8;
        #pragma unroll
        for (int nt = 0; nt < 8; nt++)
            #pragma unroll
            for (int i = 0; i < 4; i++) accA[nt][i] = 0.f;

        float a[4]; lda(a, Qx, 16*lg, 0, QX_S, row, qcol);
        #pragma unroll
        for (int kt = 0; kt < 16; kt++) {
            float b[8][2];
            #pragma unroll
            for (int nt = 0; nt < 8; nt++)
                if (nt < ntc) ldb(b[nt], kxT, 8*kt, 64*jh + 8*nt, KX_S, row, qcol);
            float an[4];
            if (kt < 15) lda(an, Qx, 16*lg, 8*(kt+1), QX_S, row, qcol);
            #pragma unroll
            for (int nt = 0; nt < 8; nt++)
                if (nt < ntc) mma8(accA[nt], a, b[nt]);
            if (kt < 15) { a[0]=an[0]; a[1]=an[1]; a[2]=an[2]; a[3]=an[3]; }
        }
    } else {
        const int t = tid - 384;                // 0..127
        dscr[t] = 0.f; dscr[t+128] = 0.f;
        const float4* gSn = (const float4*)(g_S + (size_t)(n*NCHK)*D2*DIM);
        #pragma unroll 2
        for (int it = 0; it < 16; it++) {
            int idx = t + 128*it;               // 0..2047
            int r_ = idx >> 4, g = idx & 15;
            float4 acc = make_float4(0.f,0.f,0.f,0.f);
            for (int cc = 0; cc < c; cc++) {
                float4 x = gSn[(size_t)cc*2048 + idx];
                acc.x += x.x; acc.y += x.y; acc.z += x.z; acc.w += x.w;
            }
            *(float4*)&U[r_*U_S + 4*g] =
                make_float4(tff(acc.x), tff(acc.y), tff(acc.z), tff(acc.w));
        }
        float zz = 0.f;
        for (int cc = 0; cc < c; cc++) zz += g_z[(n*NCHK + cc)*D2 + t];
        zext[t] = zz;
    }
    __syncthreads();

    // ---- Phase A epilogue: mask, tf32, store A over kxT; row-sum partials ----
    if (actA) {
        const int l_lo = 16*lg + row, l_hi = l_lo + 8;
        float slo = 0.f, shi = 0.f;
        #pragma unroll
        for (int nt = 0; nt < 8; nt++) {
            if (nt < ntc) {
                int jc = 64*jh + 8*nt + 2*qcol;
                float w0 = (jc   <= l_lo) ? accA[nt][0] : 0.f;
                float w1 = (jc+1 <= l_lo) ? accA[nt][1] : 0.f;
                float w2 = (jc   <= l_hi) ? accA[nt][2] : 0.f;
                float w3 = (jc+1 <= l_hi) ? accA[nt][3] : 0.f;
                slo += w0 + w1;  shi += w2 + w3;
                *(float2*)&kxT[l_lo*KX_S + jc] = make_float2(tff(w0), tff(w1));
                *(float2*)&kxT[l_hi*KX_S + jc] = make_float2(tff(w2), tff(w3));
            }
        }
        slo += __shfl_xor_sync(0xffffffffu, slo, 1);
        slo += __shfl_xor_sync(0xffffffffu, slo, 2);
        shi += __shfl_xor_sync(0xffffffffu, shi, 1);
        shi += __shfl_xor_sync(0xffffffffu, shi, 2);
        if (qcol == 0) {
            dscr[2*l_lo + jh] = slo;
            dscr[2*l_hi + jh] = shi;
        }
    } else {
        const int l = tid - 384;                // 0..127
        float s = 0.f;
        #pragma unroll 4
        for (int i = 0; i < 32; i++) {
            float4 qv = *(const float4*)&Qx[l*QX_S + 4*i];
            float4 zv = *(const float4*)&zext[4*i];
            s = fmaf(qv.x, zv.x, s); s = fmaf(qv.y, zv.y, s);
            s = fmaf(qv.z, zv.z, s); s = fmaf(qv.w, zv.w, s);
        }
        dscr2[l] = s;
    }
    __syncthreads();

    // ---- AV (causal) + qU fused (16 warps); denominator folded inline ----
    {
        const int smsp = wid & 3;
        const int lg2 = ((wid >> 2) & 1) ? (7 - smsp) : smsp;
        const int mg  = wid >> 3;
        const int ktmax = 2*lg2 + 2;
        float acc[4][4];
        #pragma unroll
        for (int nt = 0; nt < 4; nt++)
            #pragma unroll
            for (int i = 0; i < 4; i++) acc[nt][i] = 0.f;

        // AV: A (masked, tf32) over kxT area, B = V. Batched + pipelined.
        {
            float a[4]; lda(a, kxT, 16*lg2, 0, KX_S, row, qcol);
            #pragma unroll 4
            for (int kt = 0; kt < 16; kt++) {
                if (kt < ktmax) {
                    float b[4][2];
                    #pragma unroll
                    for (int nt = 0; nt < 4; nt++)
                        ldb(b[nt], V, 8*kt, 32*mg + 8*nt, V_S, row, qcol);
                    float an[4];
                    if (kt + 1 < ktmax) lda(an, kxT, 16*lg2, 8*(kt+1), KX_S, row, qcol);
                    #pragma unroll
                    for (int nt = 0; nt < 4; nt++) mma8(acc[nt], a, b[nt]);
                    if (kt + 1 < ktmax) { a[0]=an[0]; a[1]=an[1]; a[2]=an[2]; a[3]=an[3]; }
                }
            }
        }
        // qU: A = Qx (d' = 0..127), B = U. Batched + pipelined.
        {
            float a[4]; lda(a, Qx, 16*lg2, 0, QX_S, row, qcol);
            #pragma unroll
            for (int kt = 0; kt < 16; kt++) {
                float b[4][2];
                #pragma unroll
                for (int nt = 0; nt < 4; nt++)
                    ldb(b[nt], U, 8*kt, 32*mg + 8*nt, U_S, row, qcol);
                float an[4];
                if (kt < 15) lda(an, Qx, 16*lg2, 8*(kt+1), QX_S, row, qcol);
                #pragma unroll
                for (int nt = 0; nt < 4; nt++) mma8(acc[nt], a, b[nt]);
                if (kt < 15) { a[0]=an[0]; a[1]=an[1]; a[2]=an[2]; a[3]=an[3]; }
            }
        }

        const int l_lo = 16*lg2 + row, l_hi = l_lo + 8;
        const float rlo = 1.f / fmaxf(dscr[2*l_lo] + dscr[2*l_lo+1] + dscr2[l_lo], 1e-6f);
        const float rhi = 1.f / fmaxf(dscr[2*l_hi] + dscr[2*l_hi+1] + dscr2[l_hi], 1e-6f);
        float* ob = out + base;
        #pragma unroll
        for (int nt = 0; nt < 4; nt++) {
            int colb = 32*mg + 8*nt + 2*qcol;
            *(float2*)&ob[l_lo*64 + colb] = make_float2(acc[nt][0]*rlo, acc[nt][1]*rlo);
            *(float2*)&ob[l_hi*64 + colb] = make_float2(acc[nt][2]*rhi, acc[nt][3]*rhi);
        }
    }
}

extern "C" void kernel_launch(void* const* d_in, const int* in_sizes, int n_in,
                              void* d_out, int out_size) {
    const float* q = (const float*)d_in[0];
    const float* k = (const float*)d_in[1];
    const float* v = (const float*)d_in[2];
    float* out = (float*)d_out;

    const int smem = (128*QX_S + 128*KX_S + 128*V_S + 128*U_S
                      + 128 + 128 + 128 + 256 + 128) * 4;   // 214,016 B
    cudaFuncSetAttribute(fused_cos_attn, cudaFuncAttributeMaxDynamicSharedMemorySize, smem);
    fused_cos_attn<<<NBLK, 512, smem>>>(q, k, v, out);
}